// round 1
// baseline (speedup 1.0000x reference)
#include <cuda_runtime.h>
#include <cuda_bf16.h>
#include <cstdint>

// Indexer gather: out[i, :] = items[min(floor(clamp(indices[i],0,1)*1024), 1023), :]
// indices: [1048576] f32, items: [1024, 256] f32, out: [1048576, 256] f32.
//
// Pure streaming gather. Output writes (1.07 GB) dominate; items (1 MB) live in L2.
// One thread per float4 of output (64 threads per row), coalesced 128-bit stores.
// __stcs on the output stream keeps the hot 1 MB items table resident in L2.

static constexpr int N_INDICES = 1048576;
static constexpr int D_ITEM    = 256;
static constexpr int N_ITEMS   = 1024;
static constexpr int VEC_PER_ROW = D_ITEM / 4;          // 64 float4 per row
static constexpr long long TOTAL_VEC = (long long)N_INDICES * VEC_PER_ROW; // 67,108,864

__global__ __launch_bounds__(256, 8)
void indexer_gather_kernel(const float* __restrict__ indices,
                           const float4* __restrict__ items,
                           float4* __restrict__ out)
{
    unsigned int tid = blockIdx.x * blockDim.x + threadIdx.x;   // < 2^26, fits uint
    unsigned int row = tid >> 6;          // index row
    unsigned int col = tid & 63u;         // float4 column within row

    float x = __ldg(&indices[row]);
    x = fminf(fmaxf(x, 0.0f), 1.0f) * (float)N_ITEMS;
    int closest = min((int)floorf(x), N_ITEMS - 1);

    float4 v = __ldg(&items[(unsigned)closest * VEC_PER_ROW + col]);
    __stcs(&out[tid], v);   // streaming store: don't thrash L2 with the 1 GB output
}

extern "C" void kernel_launch(void* const* d_in, const int* in_sizes, int n_in,
                              void* d_out, int out_size)
{
    const float*  indices = (const float*)d_in[0];
    const float4* items   = (const float4*)d_in[1];
    float4*       out     = (float4*)d_out;

    const int threads = 256;
    const long long blocks = TOTAL_VEC / threads;  // 262144
    indexer_gather_kernel<<<(unsigned)blocks, threads>>>(indices, items, out);
}

// round 3
// speedup vs baseline: 1.2137x; 1.2137x over previous
#include <cuda_runtime.h>
#include <cuda_bf16.h>
#include <cstdint>

// Indexer gather: out[i, :] = items[min(floor(clamp(indices[i],0,1)*1024), 1023), :]
// indices: [1048576] f32, items: [1024, 256] f32, out: [1048576, 256] f32.
//
// R2: MLP=4 version. Each thread handles 4 independent float4 chunks in
// different rows (grid-span stride keeps every warp access fully coalesced).
// 4 independent index loads -> 4 independent item loads -> 4 streaming stores.
// This hides the ~240-cycle L2-hit latency of the item gather behind MLP
// instead of occupancy alone.

static constexpr int N_INDICES   = 1048576;
static constexpr int D_ITEM      = 256;
static constexpr int N_ITEMS     = 1024;
static constexpr int VEC_PER_ROW = D_ITEM / 4;                                  // 64
static constexpr long long TOTAL_VEC = (long long)N_INDICES * VEC_PER_ROW;      // 2^26
static constexpr int ITERS   = 4;
static constexpr int THREADS = 256;
static constexpr unsigned SPAN = (unsigned)(TOTAL_VEC / ITERS);                 // 2^24

__global__ __launch_bounds__(THREADS, 8)
void indexer_gather_kernel(const float* __restrict__ indices,
                           const float4* __restrict__ items,
                           float4* __restrict__ out)
{
    unsigned tid = blockIdx.x * blockDim.x + threadIdx.x;   // < 2^24

    unsigned v[ITERS];
    float    xi[ITERS];
    #pragma unroll
    for (int i = 0; i < ITERS; i++) {
        v[i] = tid + (unsigned)i * SPAN;            // vec index, < 2^26
        xi[i] = __ldg(&indices[v[i] >> 6]);         // 4 independent index loads
    }

    float4 val[ITERS];
    #pragma unroll
    for (int i = 0; i < ITERS; i++) {
        float x = fminf(fmaxf(xi[i], 0.0f), 1.0f) * (float)N_ITEMS;
        int closest = min((int)floorf(x), N_ITEMS - 1);
        unsigned col = v[i] & 63u;
        val[i] = __ldg(&items[(unsigned)closest * VEC_PER_ROW + col]);  // 4 independent gathers
    }

    #pragma unroll
    for (int i = 0; i < ITERS; i++) {
        __stcs(&out[v[i]], val[i]);   // streaming stores: keep 1 MB items hot in L2
    }
}

extern "C" void kernel_launch(void* const* d_in, const int* in_sizes, int n_in,
                              void* d_out, int out_size)
{
    const float*  indices = (const float*)d_in[0];
    const float4* items   = (const float4*)d_in[1];
    float4*       out     = (float4*)d_out;

    const unsigned blocks = SPAN / THREADS;   // 65536
    indexer_gather_kernel<<<blocks, THREADS>>>(indices, items, out);
}